// round 16
// baseline (speedup 1.0000x reference)
#include <cuda_runtime.h>
#include <cuda_bf16.h>

// Problem constants
#define Bsz   4
#define NODES 51
#define MODAL 4
#define SEQ   256
#define DM    128
#define DK    64
#define NBN   (Bsz * NODES)          // 204
#define GRID_N 32                    // table nodes per (bn, j)

__device__ __forceinline__ float fast_exp2(float x) {
    float y;
    asm("ex2.approx.ftz.f32 %0, %1;" : "=f"(y) : "f"(x));
    return y;
}

// ---- packed f32x2 helpers ----
typedef unsigned long long u64;
__device__ __forceinline__ u64 pk2(float lo, float hi) {
    u64 r;
    asm("mov.b64 %0, {%1, %2};" : "=l"(r) : "f"(lo), "f"(hi));
    return r;
}
__device__ __forceinline__ void upk2(u64 p, float& lo, float& hi) {
    asm("mov.b64 {%0, %1}, %2;" : "=f"(lo), "=f"(hi) : "l"(p));
}
__device__ __forceinline__ u64 mul2(u64 a, u64 b) {
    u64 r;
    asm("mul.rn.f32x2 %0, %1, %2;" : "=l"(r) : "l"(a), "l"(b));
    return r;
}
__device__ __forceinline__ u64 fma2(u64 a, u64 b, u64 c) {
    u64 r;
    asm("fma.rn.f32x2 %0, %1, %2, %3;" : "=l"(r) : "l"(a), "l"(b), "l"(c));
    return r;
}
__device__ __forceinline__ u64 add2(u64 a, u64 b) {
    u64 r;
    asm("add.rn.f32x2 %0, %1, %2;" : "=l"(r) : "l"(a), "l"(b));
    return r;
}

// ---------------------------------------------------------------------------
// ONE kernel, 102 blocks x 1024 threads; block = 2 consecutive bn.
// Halves the redundant weight-prologue L2 burst (9.8 MB vs 19.6 MB) and the
// launch ramp, keeps every proven interior component:
// Phase 1a: warps 0-15 load both x tiles (512 float4) + per-warp min/max.
// Phase 1b: ALL 32 warps: weight prologue, warp w owns rows 2w..2w+1.
// Phase 2:  warp 0 finalizes {A2, C2, Wm, Bm}.
// Phase 3:  tabulate: thread = (bnl, j, seg, g) = (wid>>4, (wid>>2)&3,
//           wid&3, lane) — exact 1024-task mapping, pure LDS broadcast,
//           64 exps/thread, seg partials combined via conflict-free smem.
// Phase 4:  Catmull-Rom interp, 2 outputs/thread (rep = bnl).
// ---------------------------------------------------------------------------
__global__ __launch_bounds__(1024, 1) void mmf_fused_kernel(
    const float* __restrict__ x,
    const float* __restrict__ Wq, const float* __restrict__ bq,
    const float* __restrict__ Wk,
    const float* __restrict__ Wv, const float* __restrict__ bv,
    float* __restrict__ out) {
    const int blk = blockIdx.x;          // handles bn = 2*blk, 2*blk+1
    const int tid = threadIdx.x;
    const int wid = tid >> 5;            // 0..31
    const int lane = tid & 31;

    __shared__ float4 sx4[2][MODAL][SEQ / 4];     // 8 KB: two x tiles
    __shared__ float sF[2][MODAL][GRID_N];        // 1 KB tables
    __shared__ float sNum[3][2][MODAL][GRID_N];   // 3 KB seg partials
    __shared__ float sDen[3][2][MODAL][GRID_N];   // 3 KB
    __shared__ float wpart[32][3];                // per-warp {pa, pc, pv}
    __shared__ float wmax[16], wmin[16];
    __shared__ float spb;                         // bv sum
    __shared__ float sc[4];                       // {A2, C2, Wm, Bm}

    // ---- Phase 1a: both x tiles + per-warp min/max (warps 0-15) ----
    if (tid < 512) {
        float4 v = ((const float4*)(x + (size_t)(2 * blk) * (MODAL * SEQ)))[tid];
        ((float4*)sx4)[tid] = v;
        float mx = fmaxf(fmaxf(v.x, v.y), fmaxf(v.z, v.w));
        float mn = fminf(fminf(v.x, v.y), fminf(v.z, v.w));
#pragma unroll
        for (int off = 16; off; off >>= 1) {
            mx = fmaxf(mx, __shfl_xor_sync(0xffffffff, mx, off));
            mn = fminf(mn, __shfl_xor_sync(0xffffffff, mn, off));
        }
        if (lane == 0) { wmax[wid] = mx; wmin[wid] = mn; }   // wid>>3 = bnl
    }

    // ---- Phase 1b: weight prologue (all 32 warps; warp w: rows 2w..2w+1) ----
    {
        float pa = 0.f, pc = 0.f, pv = 0.f;
#pragma unroll
        for (int r = 0; r < 2; r++) {
            const int row = wid * 2 + r;
            float4 q  = ((const float4*)(Wq + row * DM))[lane];
            float4 kk = ((const float4*)(Wk + row * DM))[lane];
            float4 vv = ((const float4*)(Wv + row * DM))[lane];
            float sq = (q.x + q.y) + (q.z + q.w);
            float sk = (kk.x + kk.y) + (kk.z + kk.w);
            float sv = (vv.x + vv.y) + (vv.z + vv.w);
#pragma unroll
            for (int off = 16; off; off >>= 1) {
                sq += __shfl_xor_sync(0xffffffff, sq, off);
                sk += __shfl_xor_sync(0xffffffff, sk, off);
                sv += __shfl_xor_sync(0xffffffff, sv, off);
            }
            pa = fmaf(sq, sk, pa);
            pc = fmaf(bq[row], sk, pc);   // uniform broadcast load
            pv += sv;
        }
        if (lane == 0) {
            wpart[wid][0] = pa;
            wpart[wid][1] = pc;
            wpart[wid][2] = pv;
        }
        if (wid == 31) {
            float pb = bv[lane] + bv[lane + 32];
#pragma unroll
            for (int off = 16; off; off >>= 1) pb += __shfl_xor_sync(0xffffffff, pb, off);
            if (lane == 0) spb = pb;
        }
    }
    __syncthreads();

    // ---- Phase 2: finalize scalars (warp 0; 32 partials = 32 lanes) ----
    if (wid == 0) {
        float qa = wpart[lane][0];
        float qc = wpart[lane][1];
        float qv = wpart[lane][2];
#pragma unroll
        for (int off = 16; off; off >>= 1) {
            qa += __shfl_xor_sync(0xffffffff, qa, off);
            qc += __shfl_xor_sync(0xffffffff, qc, off);
            qv += __shfl_xor_sync(0xffffffff, qv, off);
        }
        if (lane == 0) {
            const float K = 0.125f * 1.4426950408889634f;  // log2e/sqrt(64)
            sc[0] = qa * K;                                 // A2
            sc[1] = qc * K;                                 // C2
            sc[2] = qv * (1.0f / DK) * (1.0f / (MODAL - 1));  // Wm
            sc[3] = spb * (1.0f / DK);                      // Bm
        }
    }
    __syncthreads();

    // Scalars + per-bn grid params, register-resident in every thread
    const float A2  = sc[0];
    const float C2s = sc[1];
    const float Wm  = sc[2];
    const float Bm  = sc[3];

    float alo0, invh0, h0, alo1, invh1, h1;
#pragma unroll
    for (int b = 0; b < 2; b++) {
        float tmx = wmax[b * 8], tmn = wmin[b * 8];
#pragma unroll
        for (int k = 1; k < 8; k++) {
            tmx = fmaxf(tmx, wmax[b * 8 + k]);
            tmn = fminf(tmn, wmin[b * 8 + k]);
        }
        const float a_c1 = fmaf(A2, tmn, C2s);
        const float a_c2 = fmaf(A2, tmx, C2s);
        const float alo = fminf(a_c1, a_c2);
        const float ahi = fmaxf(a_c1, a_c2);
        const float h = (ahi - alo) * (1.0f / (GRID_N - 1));
        const float iv = (ahi > alo) ? (float)(GRID_N - 1) / (ahi - alo) : 0.0f;
        if (b == 0) { alo0 = alo; h0 = h; invh0 = iv; }
        else        { alo1 = alo; h1 = h; invh1 = iv; }
    }

    // ---- Phase 3: tabulate. thread = (bnl, j, seg, g); all warp-uniform
    //      except g = lane -> pure LDS broadcast ----
    {
        const int bnl = wid >> 4;              // warp-uniform
        const int j   = (wid >> 2) & 3;        // warp-uniform
        const int seg = wid & 3;               // warp-uniform t-quarter
        const int g   = lane;                  // 0..31

        const float aloB = (bnl == 0) ? alo0 : alo1;
        const float hB   = (bnl == 0) ? h0 : h1;
        const float ag = fmaf(hB, (float)g, aloB);
        const u64 a22 = pk2(ag, ag);

        u64 num01 = 0ull, num23 = 0ull;
        u64 den01 = 0ull, den23 = 0ull;
        const ulonglong2* __restrict__ row =
            ((const ulonglong2*)&sx4[bnl][j][0]) + seg * (SEQ / 16);
#pragma unroll 8
        for (int t4 = 0; t4 < SEQ / 16; t4++) {     // 16 iters x 4 elements
            ulonglong2 xt = row[t4];
            u64 p01 = mul2(a22, xt.x);
            u64 p23 = mul2(a22, xt.y);
            float p0, p1, p2, p3;
            upk2(p01, p0, p1);
            upk2(p23, p2, p3);
            float e0 = fast_exp2(p0);
            float e1 = fast_exp2(p1);
            float e2 = fast_exp2(p2);
            float e3 = fast_exp2(p3);
            u64 e01 = pk2(e0, e1);
            u64 e23 = pk2(e2, e3);
            num01 = fma2(xt.x, e01, num01);
            num23 = fma2(xt.y, e23, num23);
            den01 = add2(den01, e01);
            den23 = add2(den23, e23);
        }
        float n0, n1, n2, n3, d0, d1, d2, d3;
        upk2(num01, n0, n1);
        upk2(num23, n2, n3);
        upk2(den01, d0, d1);
        upk2(den23, d2, d3);
        float num = (n0 + n1) + (n2 + n3);
        float den = (d0 + d1) + (d2 + d3);

        if (seg != 0) {
            sNum[seg - 1][bnl][j][g] = num;
            sDen[seg - 1][bnl][j][g] = den;
        }
        __syncthreads();
        if (seg == 0) {
            num += (sNum[0][bnl][j][g] + sNum[1][bnl][j][g]) + sNum[2][bnl][j][g];
            den += (sDen[0][bnl][j][g] + sDen[1][bnl][j][g]) + sDen[2][bnl][j][g];
            sF[bnl][j][g] = __fdividef(num, den);
        }
    }
    __syncthreads();

    // ---- Phase 4: interpolate. rep = bnl; one output per (thread, rep) ----
#pragma unroll
    for (int rep = 0; rep < 2; rep++) {
        const int idx = tid + rep * 1024;      // 0..2047 over both bn
        const int i = (idx >> 8) & 3;

        const float aloB  = (rep == 0) ? alo0 : alo1;
        const float invhB = (rep == 0) ? invh0 : invh1;

        const float xi = ((const float*)sx4)[idx];
        const float a2 = fmaf(A2, xi, C2s);

        float u = (a2 - aloB) * invhB;
        int i1 = (int)floorf(u);
        i1 = max(0, min(GRID_N - 2, i1));
        float fr = fminf(fmaxf(u - (float)i1, 0.0f), 1.0f);
        const int im  = max(i1 - 1, 0);
        const int ip2 = min(i1 + 2, GRID_N - 1);

        float acc = 0.f;
#pragma unroll
        for (int j = 0; j < MODAL; j++) {
            if (j == i) continue;
            float p0 = sF[rep][j][im];
            float p1 = sF[rep][j][i1];
            float p2 = sF[rep][j][i1 + 1];
            float p3 = sF[rep][j][ip2];
            // Catmull-Rom
            float c3 = 3.0f * (p1 - p2) + (p3 - p0);
            float c2 = 2.0f * p0 - 5.0f * p1 + 4.0f * p2 - p3;
            float c1 = p2 - p0;
            float f = fmaf(0.5f * fr, fmaf(fr, fmaf(fr, c3, c2), c1), p1);
            acc += f;
        }

        out[(size_t)(2 * blk) * (MODAL * SEQ) + idx] = fmaf(Wm, acc, Bm);
    }
}

// ---------------------------------------------------------------------------
// Launch: ONE kernel, 102 blocks.
// ---------------------------------------------------------------------------
extern "C" void kernel_launch(void* const* d_in, const int* in_sizes, int n_in,
                              void* d_out, int out_size) {
    const float* x  = (const float*)d_in[0];
    const float* Wq = (const float*)d_in[1];
    const float* bq = (const float*)d_in[2];
    const float* Wk = (const float*)d_in[3];
    const float* Wv = (const float*)d_in[5];
    const float* bv = (const float*)d_in[6];
    float* out = (float*)d_out;

    mmf_fused_kernel<<<NBN / 2, 1024>>>(x, Wq, bq, Wk, Wv, bv, out);
}